// round 9
// baseline (speedup 1.0000x reference)
#include <cuda_runtime.h>
#include <cuda_bf16.h>

#define LL 2048
#define BB 64
#define KK 4
#define CC 128
#define II 512
#define NITEMS (II * BB)     // 32768
#define NPAIRS (NITEMS / 2)  // 16384
#define NPERM 24
#define WARPS_PER_BLOCK 8
#define NBLOCKS 512                          // one wave at 4 blocks/SM (148*4=592)
#define TOTAL_WARPS (NBLOCKS * WARPS_PER_BLOCK)   // 4096
#define PAIRS_PER_WARP (NPAIRS / TOTAL_WARPS)     // 4

__device__ double g_acc;
__device__ unsigned int g_count;

// permutations of {0,1,2,3}, one byte per position (little-endian)
__constant__ unsigned int c_perms[NPERM] = {
    0x03020100u, 0x02030100u, 0x03010200u, 0x01030200u, 0x02010300u, 0x01020300u,
    0x03020001u, 0x02030001u, 0x03000201u, 0x00030201u, 0x02000301u, 0x00020301u,
    0x03010002u, 0x01030002u, 0x03000102u, 0x00030102u, 0x01000302u, 0x00010302u,
    0x02010003u, 0x01020003u, 0x02000103u, 0x00020103u, 0x01000203u, 0x00010203u
};

__device__ __forceinline__ float exps4(float4 v) {
    return __expf(v.x) + __expf(v.y) + __expf(v.z) + __expf(v.w);
}

struct PairData {
    float4 f0, f1, f2, f3, f4, f5, f6, f7;   // logit fragments (2 items)
    float tw0, twt, awt, ot, oa, ps;
    int cwt, validX;
    const float* lpX;
};

__global__ __launch_bounds__(256, 4) void detpp_fused_kernel(
    const float* __restrict__ in_time,     // (L, B)
    const float* __restrict__ in_amount,   // (L, B)
    const int*   __restrict__ in_mcc,      // (L, B)
    const float* __restrict__ out_time,    // (L, B, K)
    const float* __restrict__ out_amount,  // (L, B, K)
    const float* __restrict__ out_logits,  // (L, B, K, C)
    const float* __restrict__ presence,    // (L, B, K)
    const int*   __restrict__ indices,     // (I, B)
    const int*   __restrict__ subset_lengths, // (B,)
    float*       __restrict__ out)
{
    __shared__ double s_acc;
    __shared__ unsigned int s_perms[32];
    __shared__ int s_islast;

    int tid = threadIdx.x;
    if (tid == 0) s_acc = 0.0;
    if (tid < 32) s_perms[tid] = c_perms[tid < NPERM ? tid : 0];
    __syncthreads();

    int gwarp = blockIdx.x * WARPS_PER_BLOCK + (tid >> 5);
    int lane  = tid & 31;
    int hl    = lane & 15;        // lane within half-warp
    int half  = lane >> 4;        // 0 = item0, 1 = item1 of the pair
    int k = (lane >> 2) & 3;
    int t = lane & 3;

    int c0 = half * CC + hl * 4;
    int c2 = (2 + half) * CC + hl * 4;

    // ---- loader: issues 8 float4 + scalar-gather loads for one pair ----
    auto load_pair = [&](int pair) -> PairData {
        PairData P;
        int it0 = pair * 2, it1 = it0 + 1;
        int b0 = it0 & (BB - 1), i0 = it0 >> 6;
        int b1 = it1 & (BB - 1), i1 = it1 >> 6;
        int idx0 = indices[i0 * BB + b0];
        int idx1 = indices[i1 * BB + b1];
        int row0 = idx0 * BB + b0;
        int row1 = idx1 * BB + b1;
        const float* lp0 = out_logits + (size_t)row0 * (KK * CC);
        const float* lp1 = out_logits + (size_t)row1 * (KK * CC);

        P.f0 = *reinterpret_cast<const float4*>(lp0 + c0);
        P.f1 = *reinterpret_cast<const float4*>(lp0 + c0 + 64);
        P.f2 = *reinterpret_cast<const float4*>(lp0 + c2);
        P.f3 = *reinterpret_cast<const float4*>(lp0 + c2 + 64);
        P.f4 = *reinterpret_cast<const float4*>(lp1 + c0);
        P.f5 = *reinterpret_cast<const float4*>(lp1 + c0 + 64);
        P.f6 = *reinterpret_cast<const float4*>(lp1 + c2);
        P.f7 = *reinterpret_cast<const float4*>(lp1 + c2 + 64);

        int idxX = half ? idx1 : idx0;
        int bX   = half ? b1   : b0;
        int rowX = half ? row1 : row0;
        P.lpX    = half ? lp1 : lp0;
        P.validX = half ? (i1 < subset_lengths[b1]) : (i0 < subset_lengths[b0]);

        P.tw0 = in_time[rowX];
        int r = idxX + t + 1;
        if (r >= LL) r -= LL;              // roll wrap (unreachable for valid items)
        int rr = r * BB + bX;
        P.twt = in_time[rr];
        P.awt = in_amount[rr];
        P.cwt = in_mcc[rr];
        int obase = rowX * KK + k;
        P.ot = out_time[obase];
        P.oa = out_amount[obase];
        P.ps = presence[obase];
        return P;
    };

    float warp_tot = 0.f;

    PairData A = load_pair(gwarp);         // prologue

    #pragma unroll
    for (int itr = 0; itr < PAIRS_PER_WARP; itr++) {
        // dependent gather for current pair issues first (overlaps exps)
        float sel = A.lpX[k * CC + A.cwt];

        // consume A's float4s -> frees 32 regs before next loads
        float s01 = exps4(A.f0) + exps4(A.f1);
        float s23 = exps4(A.f2) + exps4(A.f3);
        float u01 = exps4(A.f4) + exps4(A.f5);
        float u23 = exps4(A.f6) + exps4(A.f7);

        // prefetch next pair: its 10 loads fly during A's shuffle phase
        PairData B;
        if (itr + 1 < PAIRS_PER_WARP)
            B = load_pair(gwarp + (itr + 1) * TOTAL_WARPS);

        // ---- 4 interleaved half-warp butterflies (xor 1,2,4,8) ----
        #pragma unroll
        for (int o = 8; o; o >>= 1) {
            s01 += __shfl_xor_sync(0xffffffffu, s01, o);
            s23 += __shfl_xor_sync(0xffffffffu, s23, o);
            u01 += __shfl_xor_sync(0xffffffffu, u01, o);
            u23 += __shfl_xor_sync(0xffffffffu, u23, o);
        }
        float hs01 = __shfl_xor_sync(0xffffffffu, s01, 16);
        float hs23 = __shfl_xor_sync(0xffffffffu, s23, 16);
        float hu01 = __shfl_xor_sync(0xffffffffu, u01, 16);
        float hu23 = __shfl_xor_sync(0xffffffffu, u23, 16);

        float r0s = half ? hu01 : s01;
        float r1s = half ? u01  : hs01;
        float r2s = half ? hu23 : s23;
        float r3s = half ? u23  : hs23;
        float sk = (k == 0) ? r0s : (k == 1) ? r1s : (k == 2) ? r2s : r3s;

        // ---- cost entry (16 per item, one per lane) ----
        float cost = __logf(sk) - sel
                   + fabsf(A.ot - (A.twt - A.tw0))
                   + fabsf(A.oa - A.awt)
                   - A.ps;
        float soft = 0.f;
        if (t == 0) {
            soft = (A.ps > 0.f) ? A.ps + __logf(1.f + __expf(-A.ps))
                                : __logf(1.f + __expf(A.ps));
        }

        // ---- exact assignment: 24 perms per item, 2 perms per lane ----
        int base = lane & 16;
        unsigned int pm1 = s_perms[hl];
        unsigned int pm2 = s_perms[(hl < 8) ? (hl + 16) : hl];
        float pc1 = 0.f, pc2 = 0.f;
        #pragma unroll
        for (int kk = 0; kk < KK; kk++) {
            int sA = base + (kk << 2) + ((pm1 >> (8 * kk)) & 3);
            int sB = base + (kk << 2) + ((pm2 >> (8 * kk)) & 3);
            pc1 += __shfl_sync(0xffffffffu, cost, sA);
            pc2 += __shfl_sync(0xffffffffu, cost, sB);
        }
        float pc = fminf(pc1, (hl < 8) ? pc2 : 3.4e38f);
        #pragma unroll
        for (int o = 8; o; o >>= 1)
            pc = fminf(pc, __shfl_xor_sync(0xffffffffu, pc, o));

        // softplus sum within half (t==0 lanes are {0,4,8,12}+base)
        soft += __shfl_xor_sync(0xffffffffu, soft, 4);
        soft += __shfl_xor_sync(0xffffffffu, soft, 8);

        float half_tot = A.validX ? (pc + soft) : 0.f;
        half_tot += __shfl_xor_sync(0xffffffffu, half_tot, 16);
        warp_tot += half_tot;              // lane 0's value is the correct one

        A = B;                             // rotate pipeline (register rename)
    }

    if (lane == 0)
        atomicAdd(&s_acc, (double)warp_tot);

    __syncthreads();

    // ---- grid-level reduction: last block finalizes ----
    if (tid == 0) {
        atomicAdd(&g_acc, s_acc);
        __threadfence();
        unsigned int done = atomicAdd(&g_count, 1u);
        s_islast = (done == (unsigned)(NBLOCKS - 1));
    }
    __syncthreads();

    if (s_islast && tid == 0) {
        double acc = g_acc;
        int vv = 0;
        #pragma unroll
        for (int bb = 0; bb < BB; bb++) vv += subset_lengths[bb];
        out[0] = (float)(acc / (double)vv);
        g_acc = 0.0;                 // reset for next graph replay
        g_count = 0u;
    }
}

extern "C" void kernel_launch(void* const* d_in, const int* in_sizes, int n_in,
                              void* d_out, int out_size)
{
    const float* in_time        = (const float*)d_in[0];
    const float* in_amount      = (const float*)d_in[1];
    const int*   in_mcc         = (const int*)  d_in[2];
    const float* out_time       = (const float*)d_in[3];
    const float* out_amount     = (const float*)d_in[4];
    const float* out_logits     = (const float*)d_in[5];
    const float* presence       = (const float*)d_in[6];
    // d_in[7] = lengths (unused; subset_lengths already encodes validity)
    const int*   indices        = (const int*)  d_in[8];
    const int*   subset_lengths = (const int*)  d_in[9];
    float* out = (float*)d_out;

    detpp_fused_kernel<<<NBLOCKS, 256>>>(
        in_time, in_amount, in_mcc, out_time, out_amount,
        out_logits, presence, indices, subset_lengths, out);
}